// round 1
// baseline (speedup 1.0000x reference)
#include <cuda_runtime.h>

// Problem constants
#define BB 2
#define TT 2048
#define CC 1024
#define HH 16
#define DD 64

// Scratch (allocation-free rule: __device__ globals)
__device__ float g_Q[BB * HH * TT * DD];   // [B,H,T,D]
__device__ float g_K[BB * HH * TT * DD];
__device__ float g_V[BB * HH * TT * DD];
__device__ float g_Y[BB * TT * CC];        // attention output, [B,T,C]

// ---------------------------------------------------------------------------
// Tiled SGEMM config: 128x128 block tile, K-step 16, 8x8 per thread, 256 thr
// ---------------------------------------------------------------------------
#define BM 128
#define BN 128
#define BK 16
#define TM 8
#define TN 8

// QKV GEMM: qkv = x @ W_qkv + b_qkv, scattered into g_Q/g_K/g_V as [B,H,T,D]
__global__ __launch_bounds__(256) void qkv_gemm_kernel(
    const float* __restrict__ x, const float* __restrict__ W,
    const float* __restrict__ bias) {
    __shared__ float As[BK][BM];
    __shared__ float Bs[BK][BN];
    const int N = 3 * CC;  // 3072
    const int m0 = blockIdx.y * BM;
    const int n0 = blockIdx.x * BN;
    const int tid = threadIdx.x;
    const int tm0 = (tid / 16) * TM;
    const int tn0 = (tid % 16) * TN;
    float acc[TM][TN] = {};

    for (int k0 = 0; k0 < CC; k0 += BK) {
        // Load A tile (BM x BK), transpose into As[k][m]
        #pragma unroll
        for (int i = tid; i < BM * BK / 4; i += 256) {
            int m = i / 4;
            int kq = i % 4;
            float4 v = *(const float4*)&x[(size_t)(m0 + m) * CC + k0 + kq * 4];
            As[kq * 4 + 0][m] = v.x;
            As[kq * 4 + 1][m] = v.y;
            As[kq * 4 + 2][m] = v.z;
            As[kq * 4 + 3][m] = v.w;
        }
        // Load B tile (BK x BN)
        #pragma unroll
        for (int i = tid; i < BK * BN / 4; i += 256) {
            int k = i / 32;
            int nq = i % 32;
            float4 v = *(const float4*)&W[(size_t)(k0 + k) * N + n0 + nq * 4];
            *(float4*)&Bs[k][nq * 4] = v;
        }
        __syncthreads();
        #pragma unroll
        for (int k = 0; k < BK; k++) {
            float a[TM], b[TN];
            #pragma unroll
            for (int i = 0; i < TM; i++) a[i] = As[k][tm0 + i];
            #pragma unroll
            for (int j = 0; j < TN; j++) b[j] = Bs[k][tn0 + j];
            #pragma unroll
            for (int i = 0; i < TM; i++)
                #pragma unroll
                for (int j = 0; j < TN; j++) acc[i][j] += a[i] * b[j];
        }
        __syncthreads();
    }

    // Epilogue: bias + scatter to [B,H,T,D]
    #pragma unroll
    for (int i = 0; i < TM; i++) {
        int row = m0 + tm0 + i;  // flattened (b,t)
        int b = row / TT;
        int t = row % TT;
        #pragma unroll
        for (int j = 0; j < TN; j++) {
            int col = n0 + tn0 + j;
            float val = acc[i][j] + bias[col];
            int which = col / CC;  // 0=q 1=k 2=v
            int c = col % CC;
            int h = c / DD;
            int d = c % DD;
            float* dst = (which == 0) ? g_Q : (which == 1) ? g_K : g_V;
            dst[((size_t)(b * HH + h) * TT + t) * DD + d] = val;
        }
    }
}

// Proj GEMM: out = g_Y @ W_proj + b_proj
__global__ __launch_bounds__(256) void proj_gemm_kernel(
    const float* __restrict__ W, const float* __restrict__ bias,
    float* __restrict__ out) {
    __shared__ float As[BK][BM];
    __shared__ float Bs[BK][BN];
    const int N = CC;  // 1024
    const int m0 = blockIdx.y * BM;
    const int n0 = blockIdx.x * BN;
    const int tid = threadIdx.x;
    const int tm0 = (tid / 16) * TM;
    const int tn0 = (tid % 16) * TN;
    float acc[TM][TN] = {};

    for (int k0 = 0; k0 < CC; k0 += BK) {
        #pragma unroll
        for (int i = tid; i < BM * BK / 4; i += 256) {
            int m = i / 4;
            int kq = i % 4;
            float4 v = *(const float4*)&g_Y[(size_t)(m0 + m) * CC + k0 + kq * 4];
            As[kq * 4 + 0][m] = v.x;
            As[kq * 4 + 1][m] = v.y;
            As[kq * 4 + 2][m] = v.z;
            As[kq * 4 + 3][m] = v.w;
        }
        #pragma unroll
        for (int i = tid; i < BK * BN / 4; i += 256) {
            int k = i / 32;
            int nq = i % 32;
            float4 v = *(const float4*)&W[(size_t)(k0 + k) * N + n0 + nq * 4];
            *(float4*)&Bs[k][nq * 4] = v;
        }
        __syncthreads();
        #pragma unroll
        for (int k = 0; k < BK; k++) {
            float a[TM], b[TN];
            #pragma unroll
            for (int i = 0; i < TM; i++) a[i] = As[k][tm0 + i];
            #pragma unroll
            for (int j = 0; j < TN; j++) b[j] = Bs[k][tn0 + j];
            #pragma unroll
            for (int i = 0; i < TM; i++)
                #pragma unroll
                for (int j = 0; j < TN; j++) acc[i][j] += a[i] * b[j];
        }
        __syncthreads();
    }

    #pragma unroll
    for (int i = 0; i < TM; i++) {
        int row = m0 + tm0 + i;
        #pragma unroll
        for (int j = 0; j < TN; j += 4) {
            int col = n0 + tn0 + j;
            float4 v;
            v.x = acc[i][j + 0] + bias[col + 0];
            v.y = acc[i][j + 1] + bias[col + 1];
            v.z = acc[i][j + 2] + bias[col + 2];
            v.w = acc[i][j + 3] + bias[col + 3];
            *(float4*)&out[(size_t)row * N + col] = v;
        }
    }
}

// ---------------------------------------------------------------------------
// Flash attention (fp32): 1 thread = 1 query row; K/V tiles in smem
// ---------------------------------------------------------------------------
#define AT_BM 128  // query rows per block (= blockDim.x)
#define AT_BN 64   // key rows per smem tile

struct AttnState {
    float4 o[16];
    float m_i;
    float l;
};

template <bool MASKED>
__device__ __forceinline__ void attn_tile(
    const float4 (&q)[16], const float4 (*sK)[16], const float4 (*sV)[16],
    int jmax, AttnState& st) {
    #pragma unroll 1
    for (int j = 0; j < AT_BN; j++) {
        if (!MASKED || j <= jmax) {
            // s = q . K[j]
            float s0 = 0.f, s1 = 0.f, s2 = 0.f, s3 = 0.f;
            #pragma unroll
            for (int i = 0; i < 16; i++) {
                float4 kk = sK[j][i];
                s0 += q[i].x * kk.x;
                s1 += q[i].y * kk.y;
                s2 += q[i].z * kk.z;
                s3 += q[i].w * kk.w;
            }
            float s = (s0 + s1) + (s2 + s3);
            if (s > st.m_i) {
                float alpha = __expf(st.m_i - s);
                st.m_i = s;
                st.l *= alpha;
                #pragma unroll
                for (int i = 0; i < 16; i++) {
                    st.o[i].x *= alpha;
                    st.o[i].y *= alpha;
                    st.o[i].z *= alpha;
                    st.o[i].w *= alpha;
                }
            }
            float p = __expf(s - st.m_i);
            st.l += p;
            #pragma unroll
            for (int i = 0; i < 16; i++) {
                float4 vv = sV[j][i];
                st.o[i].x += p * vv.x;
                st.o[i].y += p * vv.y;
                st.o[i].z += p * vv.z;
                st.o[i].w += p * vv.w;
            }
        }
    }
}

__global__ __launch_bounds__(AT_BM) void attn_kernel() {
    __shared__ float4 sK[AT_BN][16];
    __shared__ float4 sV[AT_BN][16];
    const int bh = blockIdx.y;              // 0..B*H-1
    const int m0 = blockIdx.x * AT_BM;
    const int row = m0 + threadIdx.x;
    const float* Kbase = g_K + (size_t)bh * TT * DD;
    const float* Vbase = g_V + (size_t)bh * TT * DD;
    const float* Qrow = g_Q + (size_t)bh * TT * DD + (size_t)row * DD;

    float4 q[16];
    const float scale = 0.125f;  // 1/sqrt(64)
    #pragma unroll
    for (int i = 0; i < 16; i++) {
        float4 v = ((const float4*)Qrow)[i];
        v.x *= scale; v.y *= scale; v.z *= scale; v.w *= scale;
        q[i] = v;
    }

    AttnState st;
    #pragma unroll
    for (int i = 0; i < 16; i++) st.o[i] = make_float4(0.f, 0.f, 0.f, 0.f);
    st.m_i = -1e30f;
    st.l = 0.f;

    const int n_tiles = (m0 + AT_BM) / AT_BN;  // tiles 0..n_tiles-1
    const int n_full = m0 / AT_BN;             // fully unmasked tiles

    for (int tile = 0; tile < n_tiles; tile++) {
        int j0 = tile * AT_BN;
        __syncthreads();  // previous compute done before smem overwrite
        const float4* Kg = (const float4*)(Kbase + (size_t)j0 * DD);
        const float4* Vg = (const float4*)(Vbase + (size_t)j0 * DD);
        #pragma unroll
        for (int i = threadIdx.x; i < AT_BN * 16; i += AT_BM) {
            ((float4*)sK)[i] = Kg[i];
            ((float4*)sV)[i] = Vg[i];
        }
        __syncthreads();
        if (tile < n_full) {
            attn_tile<false>(q, sK, sV, AT_BN - 1, st);
        } else {
            attn_tile<true>(q, sK, sV, row - j0, st);
        }
    }

    // Write out: g_Y[(b*T + t)*C + h*D + d]
    float inv = 1.f / st.l;
    int b = bh / HH;
    int h = bh % HH;
    float* Yrow = g_Y + ((size_t)b * TT + row) * CC + h * DD;
    #pragma unroll
    for (int i = 0; i < 16; i++) {
        float4 v = st.o[i];
        v.x *= inv; v.y *= inv; v.z *= inv; v.w *= inv;
        ((float4*)Yrow)[i] = v;
    }
}

// ---------------------------------------------------------------------------
extern "C" void kernel_launch(void* const* d_in, const int* in_sizes, int n_in,
                              void* d_out, int out_size) {
    const float* x      = (const float*)d_in[0];
    const float* W_qkv  = (const float*)d_in[1];
    const float* b_qkv  = (const float*)d_in[2];
    const float* W_proj = (const float*)d_in[3];
    const float* b_proj = (const float*)d_in[4];
    float* out = (float*)d_out;

    dim3 g1(3 * CC / BN, (BB * TT) / BM);  // (24, 32)
    qkv_gemm_kernel<<<g1, 256>>>(x, W_qkv, b_qkv);

    dim3 g2(TT / AT_BM, BB * HH);          // (16, 32)
    attn_kernel<<<g2, AT_BM>>>();

    dim3 g3(CC / BN, (BB * TT) / BM);      // (8, 32)
    proj_gemm_kernel<<<g3, 256>>>(W_proj, b_proj, out);
}

// round 5
// speedup vs baseline: 1.3694x; 1.3694x over previous
#include <cuda_runtime.h>
#include <cuda_bf16.h>
#include <cstdint>

// Problem constants
#define BB 2
#define TT 2048
#define CC 1024
#define HH 16
#define DD 64

// Scratch (allocation-free rule: __device__ globals)
__device__ float g_Q[BB * HH * TT * DD];   // [B,H,T,D]
__device__ float g_K[BB * HH * TT * DD];
__device__ float g_V[BB * HH * TT * DD];
__device__ float g_Y[BB * TT * CC];        // attention output, [B,T,C]

__device__ __forceinline__ void mma_bf16(float (&c)[4], const uint32_t (&a)[4],
                                         const uint32_t (&b)[2]) {
    asm volatile(
        "mma.sync.aligned.m16n8k16.row.col.f32.bf16.bf16.f32 "
        "{%0,%1,%2,%3}, {%4,%5,%6,%7}, {%8,%9}, {%0,%1,%2,%3};"
        : "+f"(c[0]), "+f"(c[1]), "+f"(c[2]), "+f"(c[3])
        : "r"(a[0]), "r"(a[1]), "r"(a[2]), "r"(a[3]), "r"(b[0]), "r"(b[1]));
}

// split x into bf16 hi + bf16 lo (packed pairs along k)
__device__ __forceinline__ void split2(float x0, float x1, uint32_t& hi, uint32_t& lo) {
    __nv_bfloat16 h0 = __float2bfloat16_rn(x0);
    __nv_bfloat16 h1 = __float2bfloat16_rn(x1);
    __nv_bfloat16 l0 = __float2bfloat16_rn(x0 - __bfloat162float(h0));
    __nv_bfloat16 l1 = __float2bfloat16_rn(x1 - __bfloat162float(h1));
    hi = (uint32_t)__bfloat16_as_ushort(h1) << 16 | __bfloat16_as_ushort(h0);
    lo = (uint32_t)__bfloat16_as_ushort(l1) << 16 | __bfloat16_as_ushort(l0);
}

// ---------------------------------------------------------------------------
// bf16x3 mma.sync GEMM: C[M x NN] = A[M x 1024] * W[1024 x NN] + bias
// CTA 128x128, BK=32, 8 warps (2 M x 4 N), warp tile 64x32, m16n8k16.
// MODE 0: A = x (arg), scatter to g_Q/g_K/g_V as [B,H,T,D]
// MODE 1: A = g_Y (device symbol, NOT a host-passed arg), write to out
// ---------------------------------------------------------------------------
#define GM_BM 128
#define GM_BN 128
#define GM_BK 32
#define GM_LDS 36            // bf16 stride (72 B)
#define GM_NKT (CC / GM_BK)  // 32

template <int NN, int MODE>
__global__ __launch_bounds__(256) void gemm_mma_kernel(
    const float* __restrict__ Ain, const float* __restrict__ W,
    const float* __restrict__ bias, float* __restrict__ out) {
    __shared__ __align__(16) uint16_t Ah[GM_BM * GM_LDS];
    __shared__ __align__(16) uint16_t Al[GM_BM * GM_LDS];
    __shared__ __align__(16) uint16_t Bh[GM_BN * GM_LDS];
    __shared__ __align__(16) uint16_t Bl[GM_BN * GM_LDS];

    // CRITICAL: device-side symbol reference for MODE 1 (host code must never
    // pass a __device__ global's address as a kernel argument).
    const float* __restrict__ A = (MODE == 1) ? (const float*)g_Y : Ain;

    const int tid = threadIdx.x;
    const int lane = tid & 31;
    const int warp = tid >> 5;
    const int wm = warp & 1;    // 0..1  (M)
    const int wn = warp >> 1;   // 0..3  (N)
    const int g = lane >> 2;    // groupID 0..7
    const int t = lane & 3;     // threadID_in_group
    const int m0 = blockIdx.y * GM_BM;
    const int n0 = blockIdx.x * GM_BN;

    // B staging mapping: thread owns column n, k-quads kq = (tid>>7)*4 + i
    const int nB = tid & 127;
    const int khB = tid >> 7;

    // Staging registers
    float4 ar[4];
    float brg[4][4];   // [i][j]: W[k0 + (khB*4+i)*4 + j][n0 + nB]

    // Initial load (tile 0)
    #pragma unroll
    for (int i = 0; i < 4; i++) {
        int idx = tid + i * 256;
        ar[i] = *(const float4*)(A + (size_t)(m0 + (idx >> 3)) * CC + ((idx & 7) << 2));
        const float* wp = W + (size_t)((khB * 4 + i) * 4) * NN + n0 + nB;
        brg[i][0] = wp[0];
        brg[i][1] = wp[NN];
        brg[i][2] = wp[2 * NN];
        brg[i][3] = wp[3 * NN];
    }

    float acc[4][4][4] = {};

    #pragma unroll 1
    for (int kt = 0; kt < GM_NKT; kt++) {
        __syncthreads();   // previous tile's compute done before overwrite
        // --- store staged tile to smem (hi/lo split) ---
        #pragma unroll
        for (int i = 0; i < 4; i++) {
            int idx = tid + i * 256;
            int am = idx >> 3, akq = idx & 7;
            uint32_t h0, l0, h1, l1;
            split2(ar[i].x, ar[i].y, h0, l0);
            split2(ar[i].z, ar[i].w, h1, l1);
            *(uint2*)&Ah[am * GM_LDS + akq * 4] = make_uint2(h0, h1);
            *(uint2*)&Al[am * GM_LDS + akq * 4] = make_uint2(l0, l1);
            int kq = khB * 4 + i;
            split2(brg[i][0], brg[i][1], h0, l0);
            split2(brg[i][2], brg[i][3], h1, l1);
            *(uint2*)&Bh[nB * GM_LDS + kq * 4] = make_uint2(h0, h1);
            *(uint2*)&Bl[nB * GM_LDS + kq * 4] = make_uint2(l0, l1);
        }
        __syncthreads();

        // --- prefetch next tile into registers (overlaps compute) ---
        if (kt + 1 < GM_NKT) {
            const int k0 = (kt + 1) * GM_BK;
            #pragma unroll
            for (int i = 0; i < 4; i++) {
                int idx = tid + i * 256;
                ar[i] = *(const float4*)(A + (size_t)(m0 + (idx >> 3)) * CC + k0 + ((idx & 7) << 2));
                const float* wp = W + (size_t)(k0 + (khB * 4 + i) * 4) * NN + n0 + nB;
                brg[i][0] = wp[0];
                brg[i][1] = wp[NN];
                brg[i][2] = wp[2 * NN];
                brg[i][3] = wp[3 * NN];
            }
        }

        // --- compute: 2 x k16 steps ---
        #pragma unroll
        for (int ks = 0; ks < GM_BK; ks += 16) {
            uint32_t afh[4][4], afl[4][4], bfh[4][2], bfl[4][2];
            #pragma unroll
            for (int mf = 0; mf < 4; mf++) {
                int m = wm * 64 + mf * 16 + g;
                int kb = ks + 2 * t;
                afh[mf][0] = *(const uint32_t*)&Ah[m * GM_LDS + kb];
                afh[mf][1] = *(const uint32_t*)&Ah[(m + 8) * GM_LDS + kb];
                afh[mf][2] = *(const uint32_t*)&Ah[m * GM_LDS + kb + 8];
                afh[mf][3] = *(const uint32_t*)&Ah[(m + 8) * GM_LDS + kb + 8];
                afl[mf][0] = *(const uint32_t*)&Al[m * GM_LDS + kb];
                afl[mf][1] = *(const uint32_t*)&Al[(m + 8) * GM_LDS + kb];
                afl[mf][2] = *(const uint32_t*)&Al[m * GM_LDS + kb + 8];
                afl[mf][3] = *(const uint32_t*)&Al[(m + 8) * GM_LDS + kb + 8];
            }
            #pragma unroll
            for (int nf = 0; nf < 4; nf++) {
                int n = wn * 32 + nf * 8 + g;
                int kb = ks + 2 * t;
                bfh[nf][0] = *(const uint32_t*)&Bh[n * GM_LDS + kb];
                bfh[nf][1] = *(const uint32_t*)&Bh[n * GM_LDS + kb + 8];
                bfl[nf][0] = *(const uint32_t*)&Bl[n * GM_LDS + kb];
                bfl[nf][1] = *(const uint32_t*)&Bl[n * GM_LDS + kb + 8];
            }
            #pragma unroll
            for (int mf = 0; mf < 4; mf++)
                #pragma unroll
                for (int nf = 0; nf < 4; nf++) {
                    mma_bf16(acc[mf][nf], afh[mf], bfh[nf]);
                    mma_bf16(acc[mf][nf], afh[mf], bfl[nf]);
                    mma_bf16(acc[mf][nf], afl[mf], bfh[nf]);
                }
        }
    }

    // --- Epilogue: bias + store straight from registers ---
    #pragma unroll
    for (int mf = 0; mf < 4; mf++) {
        #pragma unroll
        for (int half = 0; half < 2; half++) {
            int row = m0 + wm * 64 + mf * 16 + g + half * 8;
            #pragma unroll
            for (int nf = 0; nf < 4; nf++) {
                int col = n0 + wn * 32 + nf * 8 + 2 * t;
                float2 v;
                v.x = acc[mf][nf][2 * half + 0] + bias[col];
                v.y = acc[mf][nf][2 * half + 1] + bias[col + 1];
                if (MODE == 0) {
                    int which = col / CC;
                    int c2 = col % CC;
                    int h = c2 / DD, d = c2 % DD;
                    int b = row / TT, tt = row % TT;
                    float* base = (which == 0) ? g_Q : (which == 1) ? g_K : g_V;
                    *(float2*)(base + (((size_t)(b * HH + h) * TT + tt) * DD + d)) = v;
                } else {
                    *(float2*)(out + (size_t)row * NN + col) = v;
                }
            }
        }
    }
}

// ---------------------------------------------------------------------------
// Flash attention (fp32): 1 thread = 1 query row; K/V tiles in smem (unchanged)
// ---------------------------------------------------------------------------
#define AT_BM 128
#define AT_BN 64

struct AttnState {
    float4 o[16];
    float m_i;
    float l;
};

template <bool MASKED>
__device__ __forceinline__ void attn_tile(
    const float4 (&q)[16], const float4 (*sK)[16], const float4 (*sV)[16],
    int jmax, AttnState& st) {
    #pragma unroll 1
    for (int j = 0; j < AT_BN; j++) {
        if (!MASKED || j <= jmax) {
            float s0 = 0.f, s1 = 0.f, s2 = 0.f, s3 = 0.f;
            #pragma unroll
            for (int i = 0; i < 16; i++) {
                float4 kk = sK[j][i];
                s0 += q[i].x * kk.x;
                s1 += q[i].y * kk.y;
                s2 += q[i].z * kk.z;
                s3 += q[i].w * kk.w;
            }
            float s = (s0 + s1) + (s2 + s3);
            if (s > st.m_i) {
                float alpha = __expf(st.m_i - s);
                st.m_i = s;
                st.l *= alpha;
                #pragma unroll
                for (int i = 0; i < 16; i++) {
                    st.o[i].x *= alpha;
                    st.o[i].y *= alpha;
                    st.o[i].z *= alpha;
                    st.o[i].w *= alpha;
                }
            }
            float p = __expf(s - st.m_i);
            st.l += p;
            #pragma unroll
            for (int i = 0; i < 16; i++) {
                float4 vv = sV[j][i];
                st.o[i].x += p * vv.x;
                st.o[i].y += p * vv.y;
                st.o[i].z += p * vv.z;
                st.o[i].w += p * vv.w;
            }
        }
    }
}

__global__ __launch_bounds__(AT_BM) void attn_kernel() {
    __shared__ float4 sK[AT_BN][16];
    __shared__ float4 sV[AT_BN][16];
    const int bh = blockIdx.y;
    const int m0 = blockIdx.x * AT_BM;
    const int row = m0 + threadIdx.x;
    const float* Kbase = g_K + (size_t)bh * TT * DD;
    const float* Vbase = g_V + (size_t)bh * TT * DD;
    const float* Qrow = g_Q + (size_t)bh * TT * DD + (size_t)row * DD;

    float4 q[16];
    const float scale = 0.125f;
    #pragma unroll
    for (int i = 0; i < 16; i++) {
        float4 v = ((const float4*)Qrow)[i];
        v.x *= scale; v.y *= scale; v.z *= scale; v.w *= scale;
        q[i] = v;
    }

    AttnState st;
    #pragma unroll
    for (int i = 0; i < 16; i++) st.o[i] = make_float4(0.f, 0.f, 0.f, 0.f);
    st.m_i = -1e30f;
    st.l = 0.f;

    const int n_tiles = (m0 + AT_BM) / AT_BN;
    const int n_full = m0 / AT_BN;

    for (int tile = 0; tile < n_tiles; tile++) {
        int j0 = tile * AT_BN;
        __syncthreads();
        const float4* Kg = (const float4*)(Kbase + (size_t)j0 * DD);
        const float4* Vg = (const float4*)(Vbase + (size_t)j0 * DD);
        #pragma unroll
        for (int i = threadIdx.x; i < AT_BN * 16; i += AT_BM) {
            ((float4*)sK)[i] = Kg[i];
            ((float4*)sV)[i] = Vg[i];
        }
        __syncthreads();
        if (tile < n_full) {
            attn_tile<false>(q, sK, sV, AT_BN - 1, st);
        } else {
            attn_tile<true>(q, sK, sV, row - j0, st);
        }
    }

    float inv = 1.f / st.l;
    int b = bh / HH;
    int h = bh % HH;
    float* Yrow = g_Y + ((size_t)b * TT + row) * CC + h * DD;
    #pragma unroll
    for (int i = 0; i < 16; i++) {
        float4 v = st.o[i];
        v.x *= inv; v.y *= inv; v.z *= inv; v.w *= inv;
        ((float4*)Yrow)[i] = v;
    }
}

// ---------------------------------------------------------------------------
extern "C" void kernel_launch(void* const* d_in, const int* in_sizes, int n_in,
                              void* d_out, int out_size) {
    const float* x      = (const float*)d_in[0];
    const float* W_qkv  = (const float*)d_in[1];
    const float* b_qkv  = (const float*)d_in[2];
    const float* W_proj = (const float*)d_in[3];
    const float* b_proj = (const float*)d_in[4];
    float* out = (float*)d_out;

    dim3 g1(3 * CC / GM_BN, (BB * TT) / GM_BM);   // (24, 32)
    gemm_mma_kernel<3 * CC, 0><<<g1, 256>>>(x, W_qkv, b_qkv, nullptr);

    dim3 g2(TT / AT_BM, BB * HH);                 // (16, 32)
    attn_kernel<<<g2, AT_BM>>>();

    dim3 g3(CC / GM_BN, (BB * TT) / GM_BM);       // (8, 32)
    // A source (g_Y) is resolved INSIDE the kernel via MODE=1.
    gemm_mma_kernel<CC, 1><<<g3, 256>>>(nullptr, W_proj, b_proj, out);
}

// round 6
// speedup vs baseline: 2.4435x; 1.7844x over previous
#include <cuda_runtime.h>
#include <cuda_bf16.h>
#include <cstdint>

// Problem constants
#define BB 2
#define TT 2048
#define CC 1024
#define HH 16
#define DD 64

// Scratch (allocation-free rule: __device__ globals)
__device__ float g_Q[BB * HH * TT * DD];   // [B,H,T,D]
__device__ float g_K[BB * HH * TT * DD];
__device__ float g_V[BB * HH * TT * DD];
__device__ float g_Y[BB * TT * CC];        // attention output, [B,T,C]

__device__ __forceinline__ void mma_bf16(float (&c)[4], const uint32_t (&a)[4],
                                         const uint32_t (&b)[2]) {
    asm volatile(
        "mma.sync.aligned.m16n8k16.row.col.f32.bf16.bf16.f32 "
        "{%0,%1,%2,%3}, {%4,%5,%6,%7}, {%8,%9}, {%0,%1,%2,%3};"
        : "+f"(c[0]), "+f"(c[1]), "+f"(c[2]), "+f"(c[3])
        : "r"(a[0]), "r"(a[1]), "r"(a[2]), "r"(a[3]), "r"(b[0]), "r"(b[1]));
}

// split x into bf16 hi + bf16 lo (packed pairs along k)
__device__ __forceinline__ void split2(float x0, float x1, uint32_t& hi, uint32_t& lo) {
    __nv_bfloat16 h0 = __float2bfloat16_rn(x0);
    __nv_bfloat16 h1 = __float2bfloat16_rn(x1);
    __nv_bfloat16 l0 = __float2bfloat16_rn(x0 - __bfloat162float(h0));
    __nv_bfloat16 l1 = __float2bfloat16_rn(x1 - __bfloat162float(h1));
    hi = (uint32_t)__bfloat16_as_ushort(h1) << 16 | __bfloat16_as_ushort(h0);
    lo = (uint32_t)__bfloat16_as_ushort(l1) << 16 | __bfloat16_as_ushort(l0);
}

// ---------------------------------------------------------------------------
// bf16x3 mma.sync GEMM (unchanged from R5)
// ---------------------------------------------------------------------------
#define GM_BM 128
#define GM_BN 128
#define GM_BK 32
#define GM_LDS 36
#define GM_NKT (CC / GM_BK)

template <int NN, int MODE>
__global__ __launch_bounds__(256) void gemm_mma_kernel(
    const float* __restrict__ Ain, const float* __restrict__ W,
    const float* __restrict__ bias, float* __restrict__ out) {
    __shared__ __align__(16) uint16_t Ah[GM_BM * GM_LDS];
    __shared__ __align__(16) uint16_t Al[GM_BM * GM_LDS];
    __shared__ __align__(16) uint16_t Bh[GM_BN * GM_LDS];
    __shared__ __align__(16) uint16_t Bl[GM_BN * GM_LDS];

    const float* __restrict__ A = (MODE == 1) ? (const float*)g_Y : Ain;

    const int tid = threadIdx.x;
    const int lane = tid & 31;
    const int warp = tid >> 5;
    const int wm = warp & 1;
    const int wn = warp >> 1;
    const int g = lane >> 2;
    const int t = lane & 3;
    const int m0 = blockIdx.y * GM_BM;
    const int n0 = blockIdx.x * GM_BN;

    const int nB = tid & 127;
    const int khB = tid >> 7;

    float4 ar[4];
    float brg[4][4];

    #pragma unroll
    for (int i = 0; i < 4; i++) {
        int idx = tid + i * 256;
        ar[i] = *(const float4*)(A + (size_t)(m0 + (idx >> 3)) * CC + ((idx & 7) << 2));
        const float* wp = W + (size_t)((khB * 4 + i) * 4) * NN + n0 + nB;
        brg[i][0] = wp[0];
        brg[i][1] = wp[NN];
        brg[i][2] = wp[2 * NN];
        brg[i][3] = wp[3 * NN];
    }

    float acc[4][4][4] = {};

    #pragma unroll 1
    for (int kt = 0; kt < GM_NKT; kt++) {
        __syncthreads();
        #pragma unroll
        for (int i = 0; i < 4; i++) {
            int idx = tid + i * 256;
            int am = idx >> 3, akq = idx & 7;
            uint32_t h0, l0, h1, l1;
            split2(ar[i].x, ar[i].y, h0, l0);
            split2(ar[i].z, ar[i].w, h1, l1);
            *(uint2*)&Ah[am * GM_LDS + akq * 4] = make_uint2(h0, h1);
            *(uint2*)&Al[am * GM_LDS + akq * 4] = make_uint2(l0, l1);
            int kq = khB * 4 + i;
            split2(brg[i][0], brg[i][1], h0, l0);
            split2(brg[i][2], brg[i][3], h1, l1);
            *(uint2*)&Bh[nB * GM_LDS + kq * 4] = make_uint2(h0, h1);
            *(uint2*)&Bl[nB * GM_LDS + kq * 4] = make_uint2(l0, l1);
        }
        __syncthreads();

        if (kt + 1 < GM_NKT) {
            const int k0 = (kt + 1) * GM_BK;
            #pragma unroll
            for (int i = 0; i < 4; i++) {
                int idx = tid + i * 256;
                ar[i] = *(const float4*)(A + (size_t)(m0 + (idx >> 3)) * CC + k0 + ((idx & 7) << 2));
                const float* wp = W + (size_t)(k0 + (khB * 4 + i) * 4) * NN + n0 + nB;
                brg[i][0] = wp[0];
                brg[i][1] = wp[NN];
                brg[i][2] = wp[2 * NN];
                brg[i][3] = wp[3 * NN];
            }
        }

        #pragma unroll
        for (int ks = 0; ks < GM_BK; ks += 16) {
            uint32_t afh[4][4], afl[4][4], bfh[4][2], bfl[4][2];
            #pragma unroll
            for (int mf = 0; mf < 4; mf++) {
                int m = wm * 64 + mf * 16 + g;
                int kb = ks + 2 * t;
                afh[mf][0] = *(const uint32_t*)&Ah[m * GM_LDS + kb];
                afh[mf][1] = *(const uint32_t*)&Ah[(m + 8) * GM_LDS + kb];
                afh[mf][2] = *(const uint32_t*)&Ah[m * GM_LDS + kb + 8];
                afh[mf][3] = *(const uint32_t*)&Ah[(m + 8) * GM_LDS + kb + 8];
                afl[mf][0] = *(const uint32_t*)&Al[m * GM_LDS + kb];
                afl[mf][1] = *(const uint32_t*)&Al[(m + 8) * GM_LDS + kb];
                afl[mf][2] = *(const uint32_t*)&Al[m * GM_LDS + kb + 8];
                afl[mf][3] = *(const uint32_t*)&Al[(m + 8) * GM_LDS + kb + 8];
            }
            #pragma unroll
            for (int nf = 0; nf < 4; nf++) {
                int n = wn * 32 + nf * 8 + g;
                int kb = ks + 2 * t;
                bfh[nf][0] = *(const uint32_t*)&Bh[n * GM_LDS + kb];
                bfh[nf][1] = *(const uint32_t*)&Bh[n * GM_LDS + kb + 8];
                bfl[nf][0] = *(const uint32_t*)&Bl[n * GM_LDS + kb];
                bfl[nf][1] = *(const uint32_t*)&Bl[n * GM_LDS + kb + 8];
            }
            #pragma unroll
            for (int mf = 0; mf < 4; mf++)
                #pragma unroll
                for (int nf = 0; nf < 4; nf++) {
                    mma_bf16(acc[mf][nf], afh[mf], bfh[nf]);
                    mma_bf16(acc[mf][nf], afh[mf], bfl[nf]);
                    mma_bf16(acc[mf][nf], afl[mf], bfh[nf]);
                }
        }
    }

    #pragma unroll
    for (int mf = 0; mf < 4; mf++) {
        #pragma unroll
        for (int half = 0; half < 2; half++) {
            int row = m0 + wm * 64 + mf * 16 + g + half * 8;
            #pragma unroll
            for (int nf = 0; nf < 4; nf++) {
                int col = n0 + wn * 32 + nf * 8 + 2 * t;
                float2 v;
                v.x = acc[mf][nf][2 * half + 0] + bias[col];
                v.y = acc[mf][nf][2 * half + 1] + bias[col + 1];
                if (MODE == 0) {
                    int which = col / CC;
                    int c2 = col % CC;
                    int h = c2 / DD, d = c2 % DD;
                    int b = row / TT, tt = row % TT;
                    float* base = (which == 0) ? g_Q : (which == 1) ? g_K : g_V;
                    *(float2*)(base + (((size_t)(b * HH + h) * TT + tt) * DD + d)) = v;
                } else {
                    *(float2*)(out + (size_t)row * NN + col) = v;
                }
            }
        }
    }
}

// ---------------------------------------------------------------------------
// Tensor-core flash attention (bf16x3 mma.sync)
// CTA: 128 q-rows, 8 warps (16 rows each), key tiles of 64, D=64.
// ---------------------------------------------------------------------------
#define AK_LDS 72   // uint16 stride: frag-load bank = 4g+t, conflict-free

__global__ __launch_bounds__(256) void attn_mma_kernel() {
    __shared__ __align__(16) uint16_t Ksh[64 * AK_LDS];
    __shared__ __align__(16) uint16_t Ksl[64 * AK_LDS];
    __shared__ __align__(16) uint16_t Vsh[64 * AK_LDS];  // transposed: [d][key]
    __shared__ __align__(16) uint16_t Vsl[64 * AK_LDS];

    const int bh = blockIdx.y;
    const int qm0 = blockIdx.x * 128;
    const int tid = threadIdx.x;
    const int lane = tid & 31;
    const int warp = tid >> 5;
    const int g = lane >> 2;
    const int t = lane & 3;

    const float* Qb = g_Q + (size_t)bh * TT * DD;
    const float* Kb = g_K + (size_t)bh * TT * DD;
    const float* Vb = g_V + (size_t)bh * TT * DD;

    // --- Q fragments in registers (scale folded in) ---
    const int r0 = qm0 + warp * 16 + g;     // this thread's row (and r0+8)
    const float* q0p = Qb + (size_t)r0 * DD;
    const float* q1p = q0p + 8 * DD;
    const float sc = 0.125f;
    uint32_t Qh[4][4], Ql[4][4];
    #pragma unroll
    for (int ks = 0; ks < 4; ks++) {
        int kb = 16 * ks + 2 * t;
        split2(q0p[kb] * sc, q0p[kb + 1] * sc, Qh[ks][0], Ql[ks][0]);
        split2(q1p[kb] * sc, q1p[kb + 1] * sc, Qh[ks][1], Ql[ks][1]);
        split2(q0p[kb + 8] * sc, q0p[kb + 9] * sc, Qh[ks][2], Ql[ks][2]);
        split2(q1p[kb + 8] * sc, q1p[kb + 9] * sc, Qh[ks][3], Ql[ks][3]);
    }

    float oacc[8][4] = {};
    float mrow[2] = {-1e30f, -1e30f};
    float lrow[2] = {0.f, 0.f};

    const int ntiles = 2 * blockIdx.x + 2;
    const int first_diag = 2 * blockIdx.x;

    #pragma unroll 1
    for (int jt = 0; jt < ntiles; jt++) {
        const int j0 = jt * 64;
        __syncthreads();
        // --- load K tile [key][d] and V tile transposed [d][key], hi/lo ---
        #pragma unroll
        for (int p = 0; p < 4; p++) {
            int idx = tid + p * 256;
            int key = idx >> 4;
            int d = (idx & 15) << 2;
            float4 kv = *(const float4*)(Kb + (size_t)(j0 + key) * DD + d);
            uint32_t h0, l0, h1, l1;
            split2(kv.x, kv.y, h0, l0);
            split2(kv.z, kv.w, h1, l1);
            *(uint2*)&Ksh[key * AK_LDS + d] = make_uint2(h0, h1);
            *(uint2*)&Ksl[key * AK_LDS + d] = make_uint2(l0, l1);
            float4 vv = *(const float4*)(Vb + (size_t)(j0 + key) * DD + d);
            #pragma unroll
            for (int c = 0; c < 4; c++) {
                float f = (&vv.x)[c];
                __nv_bfloat16 fh = __float2bfloat16_rn(f);
                __nv_bfloat16 fl = __float2bfloat16_rn(f - __bfloat162float(fh));
                Vsh[(d + c) * AK_LDS + key] = __bfloat16_as_ushort(fh);
                Vsl[(d + c) * AK_LDS + key] = __bfloat16_as_ushort(fl);
            }
        }
        __syncthreads();

        // --- S = (Q*sc) . K^T  (bf16x3) ---
        float sacc[8][4] = {};
        #pragma unroll
        for (int ks = 0; ks < 4; ks++) {
            uint32_t kfh[8][2], kfl[8][2];
            int kb = 16 * ks + 2 * t;
            #pragma unroll
            for (int nf = 0; nf < 8; nf++) {
                int n = 8 * nf + g;
                kfh[nf][0] = *(const uint32_t*)&Ksh[n * AK_LDS + kb];
                kfh[nf][1] = *(const uint32_t*)&Ksh[n * AK_LDS + kb + 8];
                kfl[nf][0] = *(const uint32_t*)&Ksl[n * AK_LDS + kb];
                kfl[nf][1] = *(const uint32_t*)&Ksl[n * AK_LDS + kb + 8];
            }
            #pragma unroll
            for (int nf = 0; nf < 8; nf++) {
                mma_bf16(sacc[nf], Qh[ks], kfh[nf]);
                mma_bf16(sacc[nf], Qh[ks], kfl[nf]);
                mma_bf16(sacc[nf], Ql[ks], kfh[nf]);
            }
        }

        // --- causal mask (diagonal tiles only) ---
        if (jt >= first_diag) {
            #pragma unroll
            for (int nf = 0; nf < 8; nf++) {
                int col = j0 + 8 * nf + 2 * t;
                if (col > r0)     sacc[nf][0] = -1e30f;
                if (col + 1 > r0) sacc[nf][1] = -1e30f;
                if (col > r0 + 8)     sacc[nf][2] = -1e30f;
                if (col + 1 > r0 + 8) sacc[nf][3] = -1e30f;
            }
        }

        // --- online softmax (per thread: 2 rows, 16 cols each + t-group) ---
        #pragma unroll
        for (int hh = 0; hh < 2; hh++) {
            float tmax = -1e30f;
            #pragma unroll
            for (int nf = 0; nf < 8; nf++)
                tmax = fmaxf(tmax, fmaxf(sacc[nf][2 * hh], sacc[nf][2 * hh + 1]));
            tmax = fmaxf(tmax, __shfl_xor_sync(0xFFFFFFFF, tmax, 1));
            tmax = fmaxf(tmax, __shfl_xor_sync(0xFFFFFFFF, tmax, 2));
            float mnew = fmaxf(mrow[hh], tmax);
            float alpha = __expf(mrow[hh] - mnew);
            mrow[hh] = mnew;
            float psum = 0.f;
            #pragma unroll
            for (int nf = 0; nf < 8; nf++) {
                float p0 = __expf(sacc[nf][2 * hh] - mnew);
                float p1 = __expf(sacc[nf][2 * hh + 1] - mnew);
                sacc[nf][2 * hh] = p0;
                sacc[nf][2 * hh + 1] = p1;
                psum += p0 + p1;
            }
            psum += __shfl_xor_sync(0xFFFFFFFF, psum, 1);
            psum += __shfl_xor_sync(0xFFFFFFFF, psum, 2);
            lrow[hh] = lrow[hh] * alpha + psum;
            #pragma unroll
            for (int nf = 0; nf < 8; nf++) {
                oacc[nf][2 * hh] *= alpha;
                oacc[nf][2 * hh + 1] *= alpha;
            }
        }

        // --- pack P (S-acc layout == A-frag layout; pure register shuffle) ---
        uint32_t Ph[4][4], Pl[4][4];
        #pragma unroll
        for (int ks2 = 0; ks2 < 4; ks2++) {
            split2(sacc[2 * ks2][0], sacc[2 * ks2][1], Ph[ks2][0], Pl[ks2][0]);
            split2(sacc[2 * ks2][2], sacc[2 * ks2][3], Ph[ks2][1], Pl[ks2][1]);
            split2(sacc[2 * ks2 + 1][0], sacc[2 * ks2 + 1][1], Ph[ks2][2], Pl[ks2][2]);
            split2(sacc[2 * ks2 + 1][2], sacc[2 * ks2 + 1][3], Ph[ks2][3], Pl[ks2][3]);
        }

        // --- O += P . V  (bf16x3) ---
        #pragma unroll
        for (int ks2 = 0; ks2 < 4; ks2++) {
            uint32_t vfh[8][2], vfl[8][2];
            int kb = 16 * ks2 + 2 * t;
            #pragma unroll
            for (int nf = 0; nf < 8; nf++) {
                int n = 8 * nf + g;
                vfh[nf][0] = *(const uint32_t*)&Vsh[n * AK_LDS + kb];
                vfh[nf][1] = *(const uint32_t*)&Vsh[n * AK_LDS + kb + 8];
                vfl[nf][0] = *(const uint32_t*)&Vsl[n * AK_LDS + kb];
                vfl[nf][1] = *(const uint32_t*)&Vsl[n * AK_LDS + kb + 8];
            }
            #pragma unroll
            for (int nf = 0; nf < 8; nf++) {
                mma_bf16(oacc[nf], Ph[ks2], vfh[nf]);
                mma_bf16(oacc[nf], Ph[ks2], vfl[nf]);
                mma_bf16(oacc[nf], Pl[ks2], vfh[nf]);
            }
        }
    }

    // --- write g_Y[(b*T + row)*C + h*64 + d] ---
    const int b = bh / HH;
    const int h = bh % HH;
    #pragma unroll
    for (int hh = 0; hh < 2; hh++) {
        float inv = 1.f / lrow[hh];
        int row = r0 + 8 * hh;
        float* yp = g_Y + ((size_t)(b * TT) + row) * CC + h * DD;
        #pragma unroll
        for (int nf = 0; nf < 8; nf++) {
            float2 v;
            v.x = oacc[nf][2 * hh] * inv;
            v.y = oacc[nf][2 * hh + 1] * inv;
            *(float2*)(yp + 8 * nf + 2 * t) = v;
        }
    }
}

// ---------------------------------------------------------------------------
extern "C" void kernel_launch(void* const* d_in, const int* in_sizes, int n_in,
                              void* d_out, int out_size) {
    const float* x      = (const float*)d_in[0];
    const float* W_qkv  = (const float*)d_in[1];
    const float* b_qkv  = (const float*)d_in[2];
    const float* W_proj = (const float*)d_in[3];
    const float* b_proj = (const float*)d_in[4];
    float* out = (float*)d_out;

    dim3 g1(3 * CC / GM_BN, (BB * TT) / GM_BM);   // (24, 32)
    gemm_mma_kernel<3 * CC, 0><<<g1, 256>>>(x, W_qkv, b_qkv, nullptr);

    dim3 g2(TT / 128, BB * HH);                   // (16, 32)
    attn_mma_kernel<<<g2, 256>>>();

    dim3 g3(CC / GM_BN, (BB * TT) / GM_BM);       // (8, 32)
    gemm_mma_kernel<CC, 1><<<g3, 256>>>(nullptr, W_proj, b_proj, out);
}

// round 7
// speedup vs baseline: 3.1977x; 1.3086x over previous
#include <cuda_runtime.h>
#include <cuda_bf16.h>
#include <cstdint>

// Problem constants
#define BB 2
#define TT 2048
#define CC 1024
#define HH 16
#define DD 64

// Scratch (allocation-free rule: __device__ globals)
__device__ float g_Q[BB * HH * TT * DD];   // [B,H,T,D]
__device__ float g_K[BB * HH * TT * DD];
__device__ float g_V[BB * HH * TT * DD];
__device__ float g_Y[BB * TT * CC];        // attention output, [B,T,C]

__device__ __forceinline__ void mma_bf16(float (&c)[4], const uint32_t (&a)[4],
                                         const uint32_t (&b)[2]) {
    asm volatile(
        "mma.sync.aligned.m16n8k16.row.col.f32.bf16.bf16.f32 "
        "{%0,%1,%2,%3}, {%4,%5,%6,%7}, {%8,%9}, {%0,%1,%2,%3};"
        : "+f"(c[0]), "+f"(c[1]), "+f"(c[2]), "+f"(c[3])
        : "r"(a[0]), "r"(a[1]), "r"(a[2]), "r"(a[3]), "r"(b[0]), "r"(b[1]));
}

__device__ __forceinline__ void mma_tf32(float (&c)[4], const uint32_t (&a)[4],
                                         const uint32_t (&b)[2]) {
    asm volatile(
        "mma.sync.aligned.m16n8k8.row.col.f32.tf32.tf32.f32 "
        "{%0,%1,%2,%3}, {%4,%5,%6,%7}, {%8,%9}, {%0,%1,%2,%3};"
        : "+f"(c[0]), "+f"(c[1]), "+f"(c[2]), "+f"(c[3])
        : "r"(a[0]), "r"(a[1]), "r"(a[2]), "r"(a[3]), "r"(b[0]), "r"(b[1]));
}

__device__ __forceinline__ float to_tf32(float x) {
    float r;
    asm("cvt.rna.tf32.f32 %0, %1;" : "=f"(r) : "f"(x));
    return r;
}

// split x into bf16 hi + bf16 lo (packed pairs along k) — attention only
__device__ __forceinline__ void split2(float x0, float x1, uint32_t& hi, uint32_t& lo) {
    __nv_bfloat16 h0 = __float2bfloat16_rn(x0);
    __nv_bfloat16 h1 = __float2bfloat16_rn(x1);
    __nv_bfloat16 l0 = __float2bfloat16_rn(x0 - __bfloat162float(h0));
    __nv_bfloat16 l1 = __float2bfloat16_rn(x1 - __bfloat162float(h1));
    hi = (uint32_t)__bfloat16_as_ushort(h1) << 16 | __bfloat16_as_ushort(h0);
    lo = (uint32_t)__bfloat16_as_ushort(l1) << 16 | __bfloat16_as_ushort(l0);
}

// ---------------------------------------------------------------------------
// tf32 mma.sync GEMM: C[M x NN] = A[M x 1024] * W[1024 x NN] + bias
// CTA 128x128, BK=32, 8 warps (2 M x 4 N), warp tile 64x32, m16n8k8.
// A smem [m][k] fp32-as-tf32, B smem transposed [n][k], stride 36 floats.
// MODE 0: A = x (arg), scatter to g_Q/g_K/g_V; MODE 1: A = g_Y symbol -> out
// ---------------------------------------------------------------------------
#define GM_BM 128
#define GM_BN 128
#define GM_BK 32
#define GM_LDS 36            // float stride (144 B): frag bank = 4g+t, clean
#define GM_NKT (CC / GM_BK)  // 32

template <int NN, int MODE>
__global__ __launch_bounds__(256) void gemm_mma_kernel(
    const float* __restrict__ Ain, const float* __restrict__ W,
    const float* __restrict__ bias, float* __restrict__ out) {
    __shared__ __align__(16) uint32_t As[GM_BM * GM_LDS];
    __shared__ __align__(16) uint32_t Bs[GM_BN * GM_LDS];

    // Device-side symbol reference for MODE 1 (host must never pass g_Y).
    const float* __restrict__ A = (MODE == 1) ? (const float*)g_Y : Ain;

    const int tid = threadIdx.x;
    const int lane = tid & 31;
    const int warp = tid >> 5;
    const int wm = warp & 1;    // 0..1  (M)
    const int wn = warp >> 1;   // 0..3  (N)
    const int g = lane >> 2;    // groupID 0..7
    const int t = lane & 3;     // threadID_in_group
    const int m0 = blockIdx.y * GM_BM;
    const int n0 = blockIdx.x * GM_BN;

    // B staging: thread owns column n = tid&127, k-quads (tid>>7)*16 + 4i
    const int nB = tid & 127;
    const int khB = tid >> 7;

    float4 ar[4];
    float brg[4][4];

    // Initial load (tile 0)
    #pragma unroll
    for (int i = 0; i < 4; i++) {
        int idx = tid + i * 256;
        ar[i] = *(const float4*)(A + (size_t)(m0 + (idx >> 3)) * CC + ((idx & 7) << 2));
        const float* wp = W + (size_t)(khB * 16 + i * 4) * NN + n0 + nB;
        brg[i][0] = wp[0];
        brg[i][1] = wp[NN];
        brg[i][2] = wp[2 * NN];
        brg[i][3] = wp[3 * NN];
    }

    float acc[4][4][4] = {};

    #pragma unroll 1
    for (int kt = 0; kt < GM_NKT; kt++) {
        __syncthreads();   // previous tile's compute done before overwrite
        // --- store staged tile to smem (cvt to tf32) ---
        #pragma unroll
        for (int i = 0; i < 4; i++) {
            int idx = tid + i * 256;
            int am = idx >> 3, akq = (idx & 7) << 2;
            float4 v = ar[i];
            uint4 u;
            u.x = __float_as_uint(to_tf32(v.x));
            u.y = __float_as_uint(to_tf32(v.y));
            u.z = __float_as_uint(to_tf32(v.z));
            u.w = __float_as_uint(to_tf32(v.w));
            *(uint4*)&As[am * GM_LDS + akq] = u;
            uint4 w;
            w.x = __float_as_uint(to_tf32(brg[i][0]));
            w.y = __float_as_uint(to_tf32(brg[i][1]));
            w.z = __float_as_uint(to_tf32(brg[i][2]));
            w.w = __float_as_uint(to_tf32(brg[i][3]));
            *(uint4*)&Bs[nB * GM_LDS + khB * 16 + i * 4] = w;
        }
        __syncthreads();

        // --- prefetch next tile into registers (overlaps compute) ---
        if (kt + 1 < GM_NKT) {
            const int k0 = (kt + 1) * GM_BK;
            #pragma unroll
            for (int i = 0; i < 4; i++) {
                int idx = tid + i * 256;
                ar[i] = *(const float4*)(A + (size_t)(m0 + (idx >> 3)) * CC + k0 + ((idx & 7) << 2));
                const float* wp = W + (size_t)(k0 + khB * 16 + i * 4) * NN + n0 + nB;
                brg[i][0] = wp[0];
                brg[i][1] = wp[NN];
                brg[i][2] = wp[2 * NN];
                brg[i][3] = wp[3 * NN];
            }
        }

        // --- compute: 4 x k8 steps ---
        #pragma unroll
        for (int ks = 0; ks < 4; ks++) {
            const int kb = ks * 8 + t;
            uint32_t af[4][4], bf[4][2];
            #pragma unroll
            for (int mf = 0; mf < 4; mf++) {
                int m = wm * 64 + mf * 16 + g;
                af[mf][0] = As[m * GM_LDS + kb];
                af[mf][1] = As[(m + 8) * GM_LDS + kb];
                af[mf][2] = As[m * GM_LDS + kb + 4];
                af[mf][3] = As[(m + 8) * GM_LDS + kb + 4];
            }
            #pragma unroll
            for (int nf = 0; nf < 4; nf++) {
                int n = wn * 32 + nf * 8 + g;
                bf[nf][0] = Bs[n * GM_LDS + kb];
                bf[nf][1] = Bs[n * GM_LDS + kb + 4];
            }
            #pragma unroll
            for (int mf = 0; mf < 4; mf++)
                #pragma unroll
                for (int nf = 0; nf < 4; nf++)
                    mma_tf32(acc[mf][nf], af[mf], bf[nf]);
        }
    }

    // --- Epilogue: bias + store straight from registers ---
    #pragma unroll
    for (int mf = 0; mf < 4; mf++) {
        #pragma unroll
        for (int half = 0; half < 2; half++) {
            int row = m0 + wm * 64 + mf * 16 + g + half * 8;
            #pragma unroll
            for (int nf = 0; nf < 4; nf++) {
                int col = n0 + wn * 32 + nf * 8 + 2 * t;
                float2 v;
                v.x = acc[mf][nf][2 * half + 0] + bias[col];
                v.y = acc[mf][nf][2 * half + 1] + bias[col + 1];
                if (MODE == 0) {
                    int which = col / CC;
                    int c2 = col % CC;
                    int h = c2 / DD, d = c2 % DD;
                    int b = row / TT, tt = row % TT;
                    float* base = (which == 0) ? g_Q : (which == 1) ? g_K : g_V;
                    *(float2*)(base + (((size_t)(b * HH + h) * TT + tt) * DD + d)) = v;
                } else {
                    *(float2*)(out + (size_t)row * NN + col) = v;
                }
            }
        }
    }
}

// ---------------------------------------------------------------------------
// Tensor-core flash attention (bf16x3 mma.sync) — unchanged from R6
// CTA: 128 q-rows, 8 warps (16 rows each), key tiles of 64, D=64.
// ---------------------------------------------------------------------------
#define AK_LDS 72   // uint16 stride: frag-load bank = 4g+t, conflict-free

__global__ __launch_bounds__(256) void attn_mma_kernel() {
    __shared__ __align__(16) uint16_t Ksh[64 * AK_LDS];
    __shared__ __align__(16) uint16_t Ksl[64 * AK_LDS];
    __shared__ __align__(16) uint16_t Vsh[64 * AK_LDS];  // transposed: [d][key]
    __shared__ __align__(16) uint16_t Vsl[64 * AK_LDS];

    const int bh = blockIdx.y;
    const int qm0 = blockIdx.x * 128;
    const int tid = threadIdx.x;
    const int lane = tid & 31;
    const int warp = tid >> 5;
    const int g = lane >> 2;
    const int t = lane & 3;

    const float* Qb = g_Q + (size_t)bh * TT * DD;
    const float* Kb = g_K + (size_t)bh * TT * DD;
    const float* Vb = g_V + (size_t)bh * TT * DD;

    const int r0 = qm0 + warp * 16 + g;
    const float* q0p = Qb + (size_t)r0 * DD;
    const float* q1p = q0p + 8 * DD;
    const float sc = 0.125f;
    uint32_t Qh[4][4], Ql[4][4];
    #pragma unroll
    for (int ks = 0; ks < 4; ks++) {
        int kb = 16 * ks + 2 * t;
        split2(q0p[kb] * sc, q0p[kb + 1] * sc, Qh[ks][0], Ql[ks][0]);
        split2(q1p[kb] * sc, q1p[kb + 1] * sc, Qh[ks][1], Ql[ks][1]);
        split2(q0p[kb + 8] * sc, q0p[kb + 9] * sc, Qh[ks][2], Ql[ks][2]);
        split2(q1p[kb + 8] * sc, q1p[kb + 9] * sc, Qh[ks][3], Ql[ks][3]);
    }

    float oacc[8][4] = {};
    float mrow[2] = {-1e30f, -1e30f};
    float lrow[2] = {0.f, 0.f};

    const int ntiles = 2 * blockIdx.x + 2;
    const int first_diag = 2 * blockIdx.x;

    #pragma unroll 1
    for (int jt = 0; jt < ntiles; jt++) {
        const int j0 = jt * 64;
        __syncthreads();
        #pragma unroll
        for (int p = 0; p < 4; p++) {
            int idx = tid + p * 256;
            int key = idx >> 4;
            int d = (idx & 15) << 2;
            float4 kv = *(const float4*)(Kb + (size_t)(j0 + key) * DD + d);
            uint32_t h0, l0, h1, l1;
            split2(kv.x, kv.y, h0, l0);
            split2(kv.z, kv.w, h1, l1);
            *(uint2*)&Ksh[key * AK_LDS + d] = make_uint2(h0, h1);
            *(uint2*)&Ksl[key * AK_LDS + d] = make_uint2(l0, l1);
            float4 vv = *(const float4*)(Vb + (size_t)(j0 + key) * DD + d);
            #pragma unroll
            for (int c = 0; c < 4; c++) {
                float f = (&vv.x)[c];
                __nv_bfloat16 fh = __float2bfloat16_rn(f);
                __nv_bfloat16 fl = __float2bfloat16_rn(f - __bfloat162float(fh));
                Vsh[(d + c) * AK_LDS + key] = __bfloat16_as_ushort(fh);
                Vsl[(d + c) * AK_LDS + key] = __bfloat16_as_ushort(fl);
            }
        }
        __syncthreads();

        float sacc[8][4] = {};
        #pragma unroll
        for (int ks = 0; ks < 4; ks++) {
            uint32_t kfh[8][2], kfl[8][2];
            int kb = 16 * ks + 2 * t;
            #pragma unroll
            for (int nf = 0; nf < 8; nf++) {
                int n = 8 * nf + g;
                kfh[nf][0] = *(const uint32_t*)&Ksh[n * AK_LDS + kb];
                kfh[nf][1] = *(const uint32_t*)&Ksh[n * AK_LDS + kb + 8];
                kfl[nf][0] = *(const uint32_t*)&Ksl[n * AK_LDS + kb];
                kfl[nf][1] = *(const uint32_t*)&Ksl[n * AK_LDS + kb + 8];
            }
            #pragma unroll
            for (int nf = 0; nf < 8; nf++) {
                mma_bf16(sacc[nf], Qh[ks], kfh[nf]);
                mma_bf16(sacc[nf], Qh[ks], kfl[nf]);
                mma_bf16(sacc[nf], Ql[ks], kfh[nf]);
            }
        }

        if (jt >= first_diag) {
            #pragma unroll
            for (int nf = 0; nf < 8; nf++) {
                int col = j0 + 8 * nf + 2 * t;
                if (col > r0)     sacc[nf][0] = -1e30f;
                if (col + 1 > r0) sacc[nf][1] = -1e30f;
                if (col > r0 + 8)     sacc[nf][2] = -1e30f;
                if (col + 1 > r0 + 8) sacc[nf][3] = -1e30f;
            }
        }

        #pragma unroll
        for (int hh = 0; hh < 2; hh++) {
            float tmax = -1e30f;
            #pragma unroll
            for (int nf = 0; nf < 8; nf++)
                tmax = fmaxf(tmax, fmaxf(sacc[nf][2 * hh], sacc[nf][2 * hh + 1]));
            tmax = fmaxf(tmax, __shfl_xor_sync(0xFFFFFFFF, tmax, 1));
            tmax = fmaxf(tmax, __shfl_xor_sync(0xFFFFFFFF, tmax, 2));
            float mnew = fmaxf(mrow[hh], tmax);
            float alpha = __expf(mrow[hh] - mnew);
            mrow[hh] = mnew;
            float psum = 0.f;
            #pragma unroll
            for (int nf = 0; nf < 8; nf++) {
                float p0 = __expf(sacc[nf][2 * hh] - mnew);
                float p1 = __expf(sacc[nf][2 * hh + 1] - mnew);
                sacc[nf][2 * hh] = p0;
                sacc[nf][2 * hh + 1] = p1;
                psum += p0 + p1;
            }
            psum += __shfl_xor_sync(0xFFFFFFFF, psum, 1);
            psum += __shfl_xor_sync(0xFFFFFFFF, psum, 2);
            lrow[hh] = lrow[hh] * alpha + psum;
            #pragma unroll
            for (int nf = 0; nf < 8; nf++) {
                oacc[nf][2 * hh] *= alpha;
                oacc[nf][2 * hh + 1] *= alpha;
            }
        }

        uint32_t Ph[4][4], Pl[4][4];
        #pragma unroll
        for (int ks2 = 0; ks2 < 4; ks2++) {
            split2(sacc[2 * ks2][0], sacc[2 * ks2][1], Ph[ks2][0], Pl[ks2][0]);
            split2(sacc[2 * ks2][2], sacc[2 * ks2][3], Ph[ks2][1], Pl[ks2][1]);
            split2(sacc[2 * ks2 + 1][0], sacc[2 * ks2 + 1][1], Ph[ks2][2], Pl[ks2][2]);
            split2(sacc[2 * ks2 + 1][2], sacc[2 * ks2 + 1][3], Ph[ks2][3], Pl[ks2][3]);
        }

        #pragma unroll
        for (int ks2 = 0; ks2 < 4; ks2++) {
            uint32_t vfh[8][2], vfl[8][2];
            int kb = 16 * ks2 + 2 * t;
            #pragma unroll
            for (int nf = 0; nf < 8; nf++) {
                int n = 8 * nf + g;
                vfh[nf][0] = *(const uint32_t*)&Vsh[n * AK_LDS + kb];
                vfh[nf][1] = *(const uint32_t*)&Vsh[n * AK_LDS + kb + 8];
                vfl[nf][0] = *(const uint32_t*)&Vsl[n * AK_LDS + kb];
                vfl[nf][1] = *(const uint32_t*)&Vsl[n * AK_LDS + kb + 8];
            }
            #pragma unroll
            for (int nf = 0; nf < 8; nf++) {
                mma_bf16(oacc[nf], Ph[ks2], vfh[nf]);
                mma_bf16(oacc[nf], Ph[ks2], vfl[nf]);
                mma_bf16(oacc[nf], Pl[ks2], vfh[nf]);
            }
        }
    }

    const int b = bh / HH;
    const int h = bh % HH;
    #pragma unroll
    for (int hh = 0; hh < 2; hh++) {
        float inv = 1.f / lrow[hh];
        int row = r0 + 8 * hh;
        float* yp = g_Y + ((size_t)(b * TT) + row) * CC + h * DD;
        #pragma unroll
        for (int nf = 0; nf < 8; nf++) {
            float2 v;
            v.x = oacc[nf][2 * hh] * inv;
            v.y = oacc[nf][2 * hh + 1] * inv;
            *(float2*)(yp + 8 * nf + 2 * t) = v;
        }
    }
}

// ---------------------------------------------------------------------------
extern "C" void kernel_launch(void* const* d_in, const int* in_sizes, int n_in,
                              void* d_out, int out_size) {
    const float* x      = (const float*)d_in[0];
    const float* W_qkv  = (const float*)d_in[1];
    const float* b_qkv  = (const float*)d_in[2];
    const float* W_proj = (const float*)d_in[3];
    const float* b_proj = (const float*)d_in[4];
    float* out = (float*)d_out;

    dim3 g1(3 * CC / GM_BN, (BB * TT) / GM_BM);   // (24, 32)
    gemm_mma_kernel<3 * CC, 0><<<g1, 256>>>(x, W_qkv, b_qkv, nullptr);

    dim3 g2(TT / 128, BB * HH);                   // (16, 32)
    attn_mma_kernel<<<g2, 256>>>();

    dim3 g3(CC / GM_BN, (BB * TT) / GM_BM);       // (8, 32)
    gemm_mma_kernel<CC, 1><<<g3, 256>>>(nullptr, W_proj, b_proj, out);
}